// round 9
// baseline (speedup 1.0000x reference)
#include <cuda_runtime.h>

#define NTHREADS 512
#define ROWS_PER_CTA 64
#define NCTA 128          // 8192 / 64
#define OUTSTR 771        // 257*3

// Thread layout (R3): u = tid & 63 (hidden unit), q = tid >> 6 (row group 0..7).
// Thread owns 8 rows R..R+7 (R = blockRow + 8q) as 4 float2 pairs.
// Warp = 32 consecutive u, same q  -> x reads are warp-uniform broadcasts.
struct SMem {
    float4 wpack[76][64];   // wpack[k][u] = {Wi,Wf,Wg,Wo}[.,k] for unit u   (77824 B)
    float4 xA[2][76][9];    // [phase][k][q] pairs 0,1 (pad 9 -> 144B k-stride)
    float4 xB[2][76][9];    // [phase][k][q] pairs 2,3
    float  w1t[64][64];     // w1t[k][u] = W1[u][k]
    float2 zhalf[8][2][4];  // [q][warp-half][pair]
};

__device__ __forceinline__ float sigf(float x) {
    return __fdividef(1.f, 1.f + __expf(-x));
}
__device__ __forceinline__ float tanh_(float x) {
    float e = __expf(2.f * x);
    return 1.f - __fdividef(2.f, e + 1.f);
}

// 4 accumulators += pair-vector * scalar, via packed fma.rn.f32x2
__device__ __forceinline__ void gate4(float sw,
                                      float2 p0, float2 p1, float2 p2, float2 p3,
                                      float2& a0, float2& a1, float2& a2, float2& a3) {
    asm("{\n\t"
        ".reg .b64 rb, rx, ra;\n\t"
        "mov.b64 rb, {%8,%8};\n\t"
        "mov.b64 rx, {%9,%10};  mov.b64 ra, {%0,%1}; fma.rn.f32x2 ra, rx, rb, ra; mov.b64 {%0,%1}, ra;\n\t"
        "mov.b64 rx, {%11,%12}; mov.b64 ra, {%2,%3}; fma.rn.f32x2 ra, rx, rb, ra; mov.b64 {%2,%3}, ra;\n\t"
        "mov.b64 rx, {%13,%14}; mov.b64 ra, {%4,%5}; fma.rn.f32x2 ra, rx, rb, ra; mov.b64 {%4,%5}, ra;\n\t"
        "mov.b64 rx, {%15,%16}; mov.b64 ra, {%6,%7}; fma.rn.f32x2 ra, rx, rb, ra; mov.b64 {%6,%7}, ra;\n\t"
        "}"
        : "+f"(a0.x), "+f"(a0.y), "+f"(a1.x), "+f"(a1.y),
          "+f"(a2.x), "+f"(a2.y), "+f"(a3.x), "+f"(a3.y)
        : "f"(sw),
          "f"(p0.x), "f"(p0.y), "f"(p1.x), "f"(p1.y),
          "f"(p2.x), "f"(p2.y), "f"(p3.x), "f"(p3.y));
}

// LSTM cell. XREG: k=2 (x2) / k=3 (x3) from registers (gen); else from SMEM phase ph.
// Inner loop is software-pipelined: prefetch k+1 operands while k's FMAs issue.
template<bool XREG>
__device__ __forceinline__ void lstm_step4(const SMem* s, int u, int q, int ph,
                                           const float2 x2[4], const float2 x3[4],
                                           float bi, float bf, float bg, float bo,
                                           float2 c4[4], float2 h4[4]) {
    float2 ai[4], af4[4], ag[4], ao[4];
#pragma unroll
    for (int p = 0; p < 4; ++p) {
        ai[p] = make_float2(bi, bi);
        af4[p] = make_float2(bf, bf);
        ag[p] = make_float2(bg, bg);
        ao[p] = make_float2(bo, bo);
    }
    const float4* wp = &s->wpack[0][u];   // stride 64 float4
    const float4* xa = &s->xA[ph][0][q];  // stride 9 float4
    const float4* xb = &s->xB[ph][0][q];

    auto doK = [&](float4 w, float4 A, float4 B) {
        float2 p0 = make_float2(A.x, A.y), p1 = make_float2(A.z, A.w);
        float2 p2 = make_float2(B.x, B.y), p3 = make_float2(B.z, B.w);
        gate4(w.x, p0, p1, p2, p3, ai[0], ai[1], ai[2], ai[3]);
        gate4(w.y, p0, p1, p2, p3, af4[0], af4[1], af4[2], af4[3]);
        gate4(w.z, p0, p1, p2, p3, ag[0], ag[1], ag[2], ag[3]);
        gate4(w.w, p0, p1, p2, p3, ao[0], ao[1], ao[2], ao[3]);
    };
    auto doKreg = [&](float4 w, const float2 x[4]) {
        gate4(w.x, x[0], x[1], x[2], x[3], ai[0], ai[1], ai[2], ai[3]);
        gate4(w.y, x[0], x[1], x[2], x[3], af4[0], af4[1], af4[2], af4[3]);
        gate4(w.z, x[0], x[1], x[2], x[3], ag[0], ag[1], ag[2], ag[3]);
        gate4(w.w, x[0], x[1], x[2], x[3], ao[0], ao[1], ao[2], ao[3]);
    };

    doK(wp[0], xa[0], xb[0]);            // k=0
    doK(wp[64], xa[9], xb[9]);           // k=1
    if (XREG) {
        doKreg(wp[2 * 64], x2);          // k=2 (dp)
        doKreg(wp[3 * 64], x3);          // k=3 (dist)
    } else {
        doK(wp[2 * 64], xa[18], xb[18]);
        doK(wp[3 * 64], xa[27], xb[27]);
    }
    // pipelined k = 4..75
    float4 wc = wp[4 * 64], ac = xa[4 * 9], bc = xb[4 * 9];
#pragma unroll 4
    for (int k = 4; k < 75; ++k) {
        float4 wn = wp[(k + 1) * 64];
        float4 an = xa[(k + 1) * 9];
        float4 bn = xb[(k + 1) * 9];
        doK(wc, ac, bc);
        wc = wn; ac = an; bc = bn;
    }
    doK(wc, ac, bc);                     // k=75

#pragma unroll
    for (int p = 0; p < 4; ++p) {
        float ix = sigf(ai[p].x), fx = sigf(af4[p].x), gx = tanh_(ag[p].x), ox = sigf(ao[p].x);
        c4[p].x = fmaf(fx, c4[p].x, ix * gx);
        h4[p].x = ox * tanh_(c4[p].x);
        float iy = sigf(ai[p].y), fy = sigf(af4[p].y), gy = tanh_(ag[p].y), oy = sigf(ao[p].y);
        c4[p].y = fmaf(fy, c4[p].y, iy * gy);
        h4[p].y = oy * tanh_(c4[p].y);
    }
}

__global__ void __launch_bounds__(NTHREADS, 1)
lstm_fused(const float* __restrict__ noise, const float* __restrict__ hist,
           const float* __restrict__ gap,   const float* __restrict__ W_ih,
           const float* __restrict__ W_hh,  const float* __restrict__ b_ih,
           const float* __restrict__ b_hh,  const float* __restrict__ W1,
           const float* __restrict__ b1,    const float* __restrict__ W2,
           const float* __restrict__ b2,    float* __restrict__ out) {
    extern __shared__ char smraw[];
    SMem* s = reinterpret_cast<SMem*>(smraw);

    const int tid = threadIdx.x;
    const int u   = tid & 63;          // hidden unit
    const int q   = tid >> 6;          // row group
    const int lane = tid & 31;
    const int wh  = (tid >> 5) & 1;    // warp half (u<32 vs u>=32)
    const int blockRow = blockIdx.x * ROWS_PER_CTA;
    const int R = blockRow + 8 * q;    // rows R..R+7

    // ---- stage weights (transposed, gate-packed) ----
    for (int idx = tid; idx < 76 * 64; idx += NTHREADS) {
        int k = idx >> 6, uu = idx & 63;
        float4 w;
        if (k < 12) {
            w.x = W_ih[uu * 12 + k];
            w.y = W_ih[(64 + uu) * 12 + k];
            w.z = W_ih[(128 + uu) * 12 + k];
            w.w = W_ih[(192 + uu) * 12 + k];
        } else {
            int kk = k - 12;
            w.x = W_hh[uu * 64 + kk];
            w.y = W_hh[(64 + uu) * 64 + kk];
            w.z = W_hh[(128 + uu) * 64 + kk];
            w.w = W_hh[(192 + uu) * 64 + kk];
        }
        s->wpack[k][uu] = w;
    }
    for (int idx = tid; idx < 64 * 64; idx += NTHREADS) {
        int uu = idx >> 6, k = idx & 63;
        s->w1t[k][uu] = W1[idx];
    }
    // h0 = 0 in phase 0
    s->xA[0][12 + u][q] = make_float4(0.f, 0.f, 0.f, 0.f);
    s->xB[0][12 + u][q] = make_float4(0.f, 0.f, 0.f, 0.f);
    // ---- copy hist_x into out[:, :64, :] ----
    for (int idx = tid; idx < ROWS_PER_CTA * 192; idx += NTHREADS) {
        int rl = idx / 192, j = idx % 192;
        out[(size_t)(blockRow + rl) * OUTSTR + j] = hist[(size_t)(blockRow + rl) * 192 + j];
    }

    const float bi = b_ih[u] + b_hh[u];
    const float bf = b_ih[64 + u] + b_hh[64 + u];
    const float bg = b_ih[128 + u] + b_hh[128 + u];
    const float bo = b_ih[192 + u] + b_hh[192 + u];
    const float b1v = b1[u];
    const float w2v = W2[u];
    const float b2v = b2[0];

    float2 c4[4], h4[4], dist4[4], pfv[4];
#pragma unroll
    for (int p = 0; p < 4; ++p) {
        c4[p] = make_float2(0.f, 0.f);
        dist4[p] = make_float2(0.f, 0.f);
        pfv[p] = make_float2(0.f, 0.f);
    }

    // ---- prefetchers: only u<12 threads touch global memory ----
    auto pre_cond = [&](int j) {
        if (u < 4) {
            int ch = (u == 3) ? 2 : u;      // u==3 tracks ch2 for the dist cumsum
#pragma unroll
            for (int p = 0; p < 4; ++p) {
                const float* hp = hist + (size_t)(R + 2 * p) * 192 + j * 3 + ch;
                pfv[p].x = hp[0];
                pfv[p].y = hp[192];
            }
        } else if (u < 12) {
            int ch = u - 4;
#pragma unroll
            for (int p = 0; p < 4; ++p) {
                const float* np = noise + (size_t)(R + 2 * p) * 2048 + j * 8 + ch;
                pfv[p].x = np[0];
                pfv[p].y = np[2048];
            }
        }
    };
    auto pre_gen = [&](int t) {
        if (u < 2) {
#pragma unroll
            for (int p = 0; p < 4; ++p) {
                const float* gp = gap + (size_t)(R + 2 * p) * 386 + t * 2 + u;
                pfv[p].x = gp[0];
                pfv[p].y = gp[386];
            }
        } else if (u >= 4 && u < 12) {
            if (t < 192) {
                int ch = u - 4;
#pragma unroll
                for (int p = 0; p < 4; ++p) {
                    const float* np = noise + (size_t)(R + 2 * p) * 2048 + (64 + t) * 8 + ch;
                    pfv[p].x = np[0];
                    pfv[p].y = np[2048];
                }
            } else {
#pragma unroll
                for (int p = 0; p < 4; ++p) pfv[p] = make_float2(0.f, 0.f);
            }
        }
    };
    auto write_h = [&](int ph) {
        s->xA[ph][12 + u][q] = make_float4(h4[0].x, h4[0].y, h4[1].x, h4[1].y);
        s->xB[ph][12 + u][q] = make_float4(h4[2].x, h4[2].y, h4[3].x, h4[3].y);
    };

    pre_cond(0);
    __syncthreads();   // staging + h0 visible

    // ================= conditioning (64 steps, 1 barrier each) =================
    for (int j = 0; j < 64; ++j) {
        int ph = j & 1;
        if (u == 3) {                     // dist = inclusive cumsum of hist ch2
#pragma unroll
            for (int p = 0; p < 4; ++p) {
                dist4[p].x += pfv[p].x;
                dist4[p].y += pfv[p].y;
            }
            s->xA[ph][3][q] = make_float4(dist4[0].x, dist4[0].y, dist4[1].x, dist4[1].y);
            s->xB[ph][3][q] = make_float4(dist4[2].x, dist4[2].y, dist4[3].x, dist4[3].y);
        } else if (u < 12) {
            s->xA[ph][u][q] = make_float4(pfv[0].x, pfv[0].y, pfv[1].x, pfv[1].y);
            s->xB[ph][u][q] = make_float4(pfv[2].x, pfv[2].y, pfv[3].x, pfv[3].y);
        }
        __syncthreads();                  // inputs + previous h visible
        if (j < 63) pre_cond(j + 1); else pre_gen(0);
        lstm_step4<false>(s, u, q, ph, nullptr, nullptr, bi, bf, bg, bo, c4, h4);
        write_h(ph ^ 1);
    }
    __syncthreads();   // last h (phase 0) + last dist (phase 1) visible

    // all threads pick up final dist from phase 1
    {
        float4 A = s->xA[1][3][q], B = s->xB[1][3][q];
        dist4[0] = make_float2(A.x, A.y);
        dist4[1] = make_float2(A.z, A.w);
        dist4[2] = make_float2(B.x, B.y);
        dist4[3] = make_float2(B.z, B.w);
    }

    // ================= generation (193 steps, 2 barriers each) =================
    for (int t = 0; t <= 192; ++t) {
        int ph = t & 1;
        // --- MLP head: a[u][row] = b1 + sum_k h[k][row]*W1[u][k] ---
        float2 a0 = make_float2(b1v, b1v), a1v = a0, a2 = a0, a3 = a0;
        {
            const float*  w1p = &s->w1t[0][u];
            const float4* ha  = &s->xA[ph][12][q];
            const float4* hb  = &s->xB[ph][12][q];
#pragma unroll 4
            for (int k = 0; k < 64; ++k) {
                float wv = w1p[k * 64];
                float4 A = ha[k * 9], B = hb[k * 9];
                gate4(wv, make_float2(A.x, A.y), make_float2(A.z, A.w),
                      make_float2(B.x, B.y), make_float2(B.z, B.w),
                      a0, a1v, a2, a3);
            }
        }
        float2 part[4];
        part[0] = make_float2(tanh_(a0.x) * w2v, tanh_(a0.y) * w2v);
        part[1] = make_float2(tanh_(a1v.x) * w2v, tanh_(a1v.y) * w2v);
        part[2] = make_float2(tanh_(a2.x) * w2v, tanh_(a2.y) * w2v);
        part[3] = make_float2(tanh_(a3.x) * w2v, tanh_(a3.y) * w2v);
        // reduce over this warp's 32 u's (all lanes share q)
#pragma unroll
        for (int p = 0; p < 4; ++p) {
#pragma unroll
            for (int m = 16; m >= 1; m >>= 1) {
                part[p].x += __shfl_xor_sync(0xffffffffu, part[p].x, m);
                part[p].y += __shfl_xor_sync(0xffffffffu, part[p].y, m);
            }
        }
        if (lane == 0) {
#pragma unroll
            for (int p = 0; p < 4; ++p) s->zhalf[q][wh][p] = part[p];
        }
        // write gap/noise inputs for this step before the same barrier
        if (u < 2 || (u >= 4 && u < 12)) {
            s->xA[ph][u][q] = make_float4(pfv[0].x, pfv[0].y, pfv[1].x, pfv[1].y);
            s->xB[ph][u][q] = make_float4(pfv[2].x, pfv[2].y, pfv[3].x, pfv[3].y);
        }
        __syncthreads();                  // zhalf + x inputs visible
        // every thread computes dp for its rows (redundant but cheap)
        float2 dp[4];
#pragma unroll
        for (int p = 0; p < 4; ++p) {
            float2 za = s->zhalf[q][0][p];
            float2 zb = s->zhalf[q][1][p];
            dp[p].x = 24.f * tanh_(za.x + zb.x + b2v);
            dp[p].y = 24.f * tanh_(za.y + zb.y + b2v);
            dist4[p].x += dp[p].x;
            dist4[p].y += dp[p].y;
        }
        int trow = (64 + t) * 3;
        if (u < 2) {
#pragma unroll
            for (int p = 0; p < 4; ++p) {
                out[(size_t)(R + 2 * p) * OUTSTR + trow + u] = pfv[p].x;
                out[(size_t)(R + 2 * p + 1) * OUTSTR + trow + u] = pfv[p].y;
            }
        } else if (u == 2) {
#pragma unroll
            for (int p = 0; p < 4; ++p) {
                out[(size_t)(R + 2 * p) * OUTSTR + trow + 2] = dp[p].x;
                out[(size_t)(R + 2 * p + 1) * OUTSTR + trow + 2] = dp[p].y;
            }
        }
        if (t == 192) break;              // last LSTM update is dead in the reference
        pre_gen(t + 1);
        lstm_step4<true>(s, u, q, ph, dp, dist4, bi, bf, bg, bo, c4, h4);
        write_h(ph ^ 1);
        __syncthreads();                  // h visible for next MLP
    }
}

extern "C" void kernel_launch(void* const* d_in, const int* in_sizes, int n_in,
                              void* d_out, int out_size) {
    const float* noise = (const float*)d_in[0];
    const float* hist  = (const float*)d_in[1];
    const float* gap   = (const float*)d_in[2];
    const float* W_ih  = (const float*)d_in[3];
    const float* W_hh  = (const float*)d_in[4];
    const float* b_ih  = (const float*)d_in[5];
    const float* b_hh  = (const float*)d_in[6];
    const float* W1    = (const float*)d_in[7];
    const float* b1    = (const float*)d_in[8];
    const float* W2    = (const float*)d_in[9];
    const float* b2    = (const float*)d_in[10];
    float* out = (float*)d_out;

    size_t smem = sizeof(SMem);
    cudaFuncSetAttribute(lstm_fused, cudaFuncAttributeMaxDynamicSharedMemorySize, (int)smem);
    lstm_fused<<<NCTA, NTHREADS, smem>>>(noise, hist, gap, W_ih, W_hh, b_ih, b_hh,
                                         W1, b1, W2, b2, out);
}

// round 10
// speedup vs baseline: 1.0009x; 1.0009x over previous
#include <cuda_runtime.h>

#define NTHREADS 512
#define ROWS_PER_CTA 64
#define NCTA 128          // 8192 / 64
#define OUTSTR 771        // 257*3

// Thread layout (R3): u = tid & 63 (hidden unit), q = tid >> 6 (row group 0..7).
// Thread owns 8 rows R..R+7 (R = blockRow + 8q) as 4 float2 pairs.
// Warp = 32 consecutive u, same q  -> x reads are warp-uniform broadcasts.
struct SMem {
    float4 wpack[76][64];   // wpack[k][u] = {Wi,Wf,Wg,Wo}[.,k] for unit u   (77824 B)
    float4 xA[2][76][9];    // [phase][k][q] pairs 0,1 (pad 9 -> 144B k-stride)
    float4 xB[2][76][9];    // [phase][k][q] pairs 2,3
    float  w1t[64][64];     // w1t[k][u] = W1[u][k]
    float2 zhalf[8][2][4];  // [q][warp-half][pair]
};

__device__ __forceinline__ float sigf(float x) {
    return __fdividef(1.f, 1.f + __expf(-x));
}
__device__ __forceinline__ float tanh_(float x) {
    float e = __expf(2.f * x);
    return 1.f - __fdividef(2.f, e + 1.f);
}

// 4 accumulators += pair-vector * scalar, via packed fma.rn.f32x2
__device__ __forceinline__ void gate4(float sw,
                                      float2 p0, float2 p1, float2 p2, float2 p3,
                                      float2& a0, float2& a1, float2& a2, float2& a3) {
    asm("{\n\t"
        ".reg .b64 rb, rx, ra;\n\t"
        "mov.b64 rb, {%8,%8};\n\t"
        "mov.b64 rx, {%9,%10};  mov.b64 ra, {%0,%1}; fma.rn.f32x2 ra, rx, rb, ra; mov.b64 {%0,%1}, ra;\n\t"
        "mov.b64 rx, {%11,%12}; mov.b64 ra, {%2,%3}; fma.rn.f32x2 ra, rx, rb, ra; mov.b64 {%2,%3}, ra;\n\t"
        "mov.b64 rx, {%13,%14}; mov.b64 ra, {%4,%5}; fma.rn.f32x2 ra, rx, rb, ra; mov.b64 {%4,%5}, ra;\n\t"
        "mov.b64 rx, {%15,%16}; mov.b64 ra, {%6,%7}; fma.rn.f32x2 ra, rx, rb, ra; mov.b64 {%6,%7}, ra;\n\t"
        "}"
        : "+f"(a0.x), "+f"(a0.y), "+f"(a1.x), "+f"(a1.y),
          "+f"(a2.x), "+f"(a2.y), "+f"(a3.x), "+f"(a3.y)
        : "f"(sw),
          "f"(p0.x), "f"(p0.y), "f"(p1.x), "f"(p1.y),
          "f"(p2.x), "f"(p2.y), "f"(p3.x), "f"(p3.y));
}

// LSTM cell. XREG: k=2 (x2) / k=3 (x3) from registers (gen); else from SMEM phase ph.
// Inner loop is software-pipelined: prefetch k+1 operands while k's FMAs issue.
template<bool XREG>
__device__ __forceinline__ void lstm_step4(const SMem* s, int u, int q, int ph,
                                           const float2 x2[4], const float2 x3[4],
                                           float bi, float bf, float bg, float bo,
                                           float2 c4[4], float2 h4[4]) {
    float2 ai[4], af4[4], ag[4], ao[4];
#pragma unroll
    for (int p = 0; p < 4; ++p) {
        ai[p] = make_float2(bi, bi);
        af4[p] = make_float2(bf, bf);
        ag[p] = make_float2(bg, bg);
        ao[p] = make_float2(bo, bo);
    }
    const float4* wp = &s->wpack[0][u];   // stride 64 float4
    const float4* xa = &s->xA[ph][0][q];  // stride 9 float4
    const float4* xb = &s->xB[ph][0][q];

    auto doK = [&](float4 w, float4 A, float4 B) {
        float2 p0 = make_float2(A.x, A.y), p1 = make_float2(A.z, A.w);
        float2 p2 = make_float2(B.x, B.y), p3 = make_float2(B.z, B.w);
        gate4(w.x, p0, p1, p2, p3, ai[0], ai[1], ai[2], ai[3]);
        gate4(w.y, p0, p1, p2, p3, af4[0], af4[1], af4[2], af4[3]);
        gate4(w.z, p0, p1, p2, p3, ag[0], ag[1], ag[2], ag[3]);
        gate4(w.w, p0, p1, p2, p3, ao[0], ao[1], ao[2], ao[3]);
    };
    auto doKreg = [&](float4 w, const float2 x[4]) {
        gate4(w.x, x[0], x[1], x[2], x[3], ai[0], ai[1], ai[2], ai[3]);
        gate4(w.y, x[0], x[1], x[2], x[3], af4[0], af4[1], af4[2], af4[3]);
        gate4(w.z, x[0], x[1], x[2], x[3], ag[0], ag[1], ag[2], ag[3]);
        gate4(w.w, x[0], x[1], x[2], x[3], ao[0], ao[1], ao[2], ao[3]);
    };

    doK(wp[0], xa[0], xb[0]);            // k=0
    doK(wp[64], xa[9], xb[9]);           // k=1
    if (XREG) {
        doKreg(wp[2 * 64], x2);          // k=2 (dp)
        doKreg(wp[3 * 64], x3);          // k=3 (dist)
    } else {
        doK(wp[2 * 64], xa[18], xb[18]);
        doK(wp[3 * 64], xa[27], xb[27]);
    }
    // pipelined k = 4..75
    float4 wc = wp[4 * 64], ac = xa[4 * 9], bc = xb[4 * 9];
#pragma unroll 4
    for (int k = 4; k < 75; ++k) {
        float4 wn = wp[(k + 1) * 64];
        float4 an = xa[(k + 1) * 9];
        float4 bn = xb[(k + 1) * 9];
        doK(wc, ac, bc);
        wc = wn; ac = an; bc = bn;
    }
    doK(wc, ac, bc);                     // k=75

#pragma unroll
    for (int p = 0; p < 4; ++p) {
        float ix = sigf(ai[p].x), fx = sigf(af4[p].x), gx = tanh_(ag[p].x), ox = sigf(ao[p].x);
        c4[p].x = fmaf(fx, c4[p].x, ix * gx);
        h4[p].x = ox * tanh_(c4[p].x);
        float iy = sigf(ai[p].y), fy = sigf(af4[p].y), gy = tanh_(ag[p].y), oy = sigf(ao[p].y);
        c4[p].y = fmaf(fy, c4[p].y, iy * gy);
        h4[p].y = oy * tanh_(c4[p].y);
    }
}

__global__ void __launch_bounds__(NTHREADS, 1)
lstm_fused(const float* __restrict__ noise, const float* __restrict__ hist,
           const float* __restrict__ gap,   const float* __restrict__ W_ih,
           const float* __restrict__ W_hh,  const float* __restrict__ b_ih,
           const float* __restrict__ b_hh,  const float* __restrict__ W1,
           const float* __restrict__ b1,    const float* __restrict__ W2,
           const float* __restrict__ b2,    float* __restrict__ out) {
    extern __shared__ char smraw[];
    SMem* s = reinterpret_cast<SMem*>(smraw);

    const int tid = threadIdx.x;
    const int u   = tid & 63;          // hidden unit
    const int q   = tid >> 6;          // row group
    const int lane = tid & 31;
    const int wh  = (tid >> 5) & 1;    // warp half (u<32 vs u>=32)
    const int blockRow = blockIdx.x * ROWS_PER_CTA;
    const int R = blockRow + 8 * q;    // rows R..R+7

    // ---- stage weights (transposed, gate-packed) ----
    for (int idx = tid; idx < 76 * 64; idx += NTHREADS) {
        int k = idx >> 6, uu = idx & 63;
        float4 w;
        if (k < 12) {
            w.x = W_ih[uu * 12 + k];
            w.y = W_ih[(64 + uu) * 12 + k];
            w.z = W_ih[(128 + uu) * 12 + k];
            w.w = W_ih[(192 + uu) * 12 + k];
        } else {
            int kk = k - 12;
            w.x = W_hh[uu * 64 + kk];
            w.y = W_hh[(64 + uu) * 64 + kk];
            w.z = W_hh[(128 + uu) * 64 + kk];
            w.w = W_hh[(192 + uu) * 64 + kk];
        }
        s->wpack[k][uu] = w;
    }
    for (int idx = tid; idx < 64 * 64; idx += NTHREADS) {
        int uu = idx >> 6, k = idx & 63;
        s->w1t[k][uu] = W1[idx];
    }
    // h0 = 0 in phase 0
    s->xA[0][12 + u][q] = make_float4(0.f, 0.f, 0.f, 0.f);
    s->xB[0][12 + u][q] = make_float4(0.f, 0.f, 0.f, 0.f);
    // ---- copy hist_x into out[:, :64, :] ----
    for (int idx = tid; idx < ROWS_PER_CTA * 192; idx += NTHREADS) {
        int rl = idx / 192, j = idx % 192;
        out[(size_t)(blockRow + rl) * OUTSTR + j] = hist[(size_t)(blockRow + rl) * 192 + j];
    }

    const float bi = b_ih[u] + b_hh[u];
    const float bf = b_ih[64 + u] + b_hh[64 + u];
    const float bg = b_ih[128 + u] + b_hh[128 + u];
    const float bo = b_ih[192 + u] + b_hh[192 + u];
    const float b1v = b1[u];
    const float w2v = W2[u];
    const float b2v = b2[0];

    float2 c4[4], h4[4], dist4[4], pfv[4];
#pragma unroll
    for (int p = 0; p < 4; ++p) {
        c4[p] = make_float2(0.f, 0.f);
        dist4[p] = make_float2(0.f, 0.f);
        pfv[p] = make_float2(0.f, 0.f);
    }

    // ---- prefetchers: only u<12 threads touch global memory ----
    auto pre_cond = [&](int j) {
        if (u < 4) {
            int ch = (u == 3) ? 2 : u;      // u==3 tracks ch2 for the dist cumsum
#pragma unroll
            for (int p = 0; p < 4; ++p) {
                const float* hp = hist + (size_t)(R + 2 * p) * 192 + j * 3 + ch;
                pfv[p].x = hp[0];
                pfv[p].y = hp[192];
            }
        } else if (u < 12) {
            int ch = u - 4;
#pragma unroll
            for (int p = 0; p < 4; ++p) {
                const float* np = noise + (size_t)(R + 2 * p) * 2048 + j * 8 + ch;
                pfv[p].x = np[0];
                pfv[p].y = np[2048];
            }
        }
    };
    auto pre_gen = [&](int t) {
        if (u < 2) {
#pragma unroll
            for (int p = 0; p < 4; ++p) {
                const float* gp = gap + (size_t)(R + 2 * p) * 386 + t * 2 + u;
                pfv[p].x = gp[0];
                pfv[p].y = gp[386];
            }
        } else if (u >= 4 && u < 12) {
            if (t < 192) {
                int ch = u - 4;
#pragma unroll
                for (int p = 0; p < 4; ++p) {
                    const float* np = noise + (size_t)(R + 2 * p) * 2048 + (64 + t) * 8 + ch;
                    pfv[p].x = np[0];
                    pfv[p].y = np[2048];
                }
            } else {
#pragma unroll
                for (int p = 0; p < 4; ++p) pfv[p] = make_float2(0.f, 0.f);
            }
        }
    };
    auto write_h = [&](int ph) {
        s->xA[ph][12 + u][q] = make_float4(h4[0].x, h4[0].y, h4[1].x, h4[1].y);
        s->xB[ph][12 + u][q] = make_float4(h4[2].x, h4[2].y, h4[3].x, h4[3].y);
    };

    pre_cond(0);
    __syncthreads();   // staging + h0 visible

    // ================= conditioning (64 steps, 1 barrier each) =================
    for (int j = 0; j < 64; ++j) {
        int ph = j & 1;
        if (u == 3) {                     // dist = inclusive cumsum of hist ch2
#pragma unroll
            for (int p = 0; p < 4; ++p) {
                dist4[p].x += pfv[p].x;
                dist4[p].y += pfv[p].y;
            }
            s->xA[ph][3][q] = make_float4(dist4[0].x, dist4[0].y, dist4[1].x, dist4[1].y);
            s->xB[ph][3][q] = make_float4(dist4[2].x, dist4[2].y, dist4[3].x, dist4[3].y);
        } else if (u < 12) {
            s->xA[ph][u][q] = make_float4(pfv[0].x, pfv[0].y, pfv[1].x, pfv[1].y);
            s->xB[ph][u][q] = make_float4(pfv[2].x, pfv[2].y, pfv[3].x, pfv[3].y);
        }
        __syncthreads();                  // inputs + previous h visible
        if (j < 63) pre_cond(j + 1); else pre_gen(0);
        lstm_step4<false>(s, u, q, ph, nullptr, nullptr, bi, bf, bg, bo, c4, h4);
        write_h(ph ^ 1);
    }
    __syncthreads();   // last h (phase 0) + last dist (phase 1) visible

    // all threads pick up final dist from phase 1
    {
        float4 A = s->xA[1][3][q], B = s->xB[1][3][q];
        dist4[0] = make_float2(A.x, A.y);
        dist4[1] = make_float2(A.z, A.w);
        dist4[2] = make_float2(B.x, B.y);
        dist4[3] = make_float2(B.z, B.w);
    }

    // ================= generation (193 steps, 2 barriers each) =================
    for (int t = 0; t <= 192; ++t) {
        int ph = t & 1;
        // --- MLP head: a[u][row] = b1 + sum_k h[k][row]*W1[u][k] ---
        float2 a0 = make_float2(b1v, b1v), a1v = a0, a2 = a0, a3 = a0;
        {
            const float*  w1p = &s->w1t[0][u];
            const float4* ha  = &s->xA[ph][12][q];
            const float4* hb  = &s->xB[ph][12][q];
#pragma unroll 4
            for (int k = 0; k < 64; ++k) {
                float wv = w1p[k * 64];
                float4 A = ha[k * 9], B = hb[k * 9];
                gate4(wv, make_float2(A.x, A.y), make_float2(A.z, A.w),
                      make_float2(B.x, B.y), make_float2(B.z, B.w),
                      a0, a1v, a2, a3);
            }
        }
        float2 part[4];
        part[0] = make_float2(tanh_(a0.x) * w2v, tanh_(a0.y) * w2v);
        part[1] = make_float2(tanh_(a1v.x) * w2v, tanh_(a1v.y) * w2v);
        part[2] = make_float2(tanh_(a2.x) * w2v, tanh_(a2.y) * w2v);
        part[3] = make_float2(tanh_(a3.x) * w2v, tanh_(a3.y) * w2v);
        // reduce over this warp's 32 u's (all lanes share q)
#pragma unroll
        for (int p = 0; p < 4; ++p) {
#pragma unroll
            for (int m = 16; m >= 1; m >>= 1) {
                part[p].x += __shfl_xor_sync(0xffffffffu, part[p].x, m);
                part[p].y += __shfl_xor_sync(0xffffffffu, part[p].y, m);
            }
        }
        if (lane == 0) {
#pragma unroll
            for (int p = 0; p < 4; ++p) s->zhalf[q][wh][p] = part[p];
        }
        // write gap/noise inputs for this step before the same barrier
        if (u < 2 || (u >= 4 && u < 12)) {
            s->xA[ph][u][q] = make_float4(pfv[0].x, pfv[0].y, pfv[1].x, pfv[1].y);
            s->xB[ph][u][q] = make_float4(pfv[2].x, pfv[2].y, pfv[3].x, pfv[3].y);
        }
        __syncthreads();                  // zhalf + x inputs visible
        // every thread computes dp for its rows (redundant but cheap)
        float2 dp[4];
#pragma unroll
        for (int p = 0; p < 4; ++p) {
            float2 za = s->zhalf[q][0][p];
            float2 zb = s->zhalf[q][1][p];
            dp[p].x = 24.f * tanh_(za.x + zb.x + b2v);
            dp[p].y = 24.f * tanh_(za.y + zb.y + b2v);
            dist4[p].x += dp[p].x;
            dist4[p].y += dp[p].y;
        }
        int trow = (64 + t) * 3;
        if (u < 2) {
#pragma unroll
            for (int p = 0; p < 4; ++p) {
                out[(size_t)(R + 2 * p) * OUTSTR + trow + u] = pfv[p].x;
                out[(size_t)(R + 2 * p + 1) * OUTSTR + trow + u] = pfv[p].y;
            }
        } else if (u == 2) {
#pragma unroll
            for (int p = 0; p < 4; ++p) {
                out[(size_t)(R + 2 * p) * OUTSTR + trow + 2] = dp[p].x;
                out[(size_t)(R + 2 * p + 1) * OUTSTR + trow + 2] = dp[p].y;
            }
        }
        if (t == 192) break;              // last LSTM update is dead in the reference
        pre_gen(t + 1);
        lstm_step4<true>(s, u, q, ph, dp, dist4, bi, bf, bg, bo, c4, h4);
        write_h(ph ^ 1);
        __syncthreads();                  // h visible for next MLP
    }
}

extern "C" void kernel_launch(void* const* d_in, const int* in_sizes, int n_in,
                              void* d_out, int out_size) {
    const float* noise = (const float*)d_in[0];
    const float* hist  = (const float*)d_in[1];
    const float* gap   = (const float*)d_in[2];
    const float* W_ih  = (const float*)d_in[3];
    const float* W_hh  = (const float*)d_in[4];
    const float* b_ih  = (const float*)d_in[5];
    const float* b_hh  = (const float*)d_in[6];
    const float* W1    = (const float*)d_in[7];
    const float* b1    = (const float*)d_in[8];
    const float* W2    = (const float*)d_in[9];
    const float* b2    = (const float*)d_in[10];
    float* out = (float*)d_out;

    size_t smem = sizeof(SMem);
    cudaFuncSetAttribute(lstm_fused, cudaFuncAttributeMaxDynamicSharedMemorySize, (int)smem);
    lstm_fused<<<NCTA, NTHREADS, smem>>>(noise, hist, gap, W_ih, W_hh, b_ih, b_hh,
                                         W1, b1, W2, b2, out);
}

// round 11
// speedup vs baseline: 1.0808x; 1.0798x over previous
#include <cuda_runtime.h>

#define NTHREADS 256
#define ROWS_PER_CTA 64
#define NCTA 128          // 8192 / 64
#define OUTSTR 771        // 257*3

// Thread layout: u = tid & 63 (hidden unit), q = tid >> 6 (row group 0..3).
// Thread owns 16 rows R..R+15 (R = blockRow + 16q) as 8 float2 pairs.
// Warp = 32 consecutive u, same q -> x reads are warp-uniform broadcasts.
// x tile: float4 xbuf[phase][k*21 + set*5 + q], set=pair>>1 (4 sets of 2 pairs).
// u-stride for h-stores = 21 float4 = 84 words -> conflict-free STS.128.
struct SMem {
    float4 wpack[76][64];   // {Wi,Wf,Wg,Wo}[.,k] for unit u        (77824 B)
    float4 xbuf[2][76*21];  // [phase][k][set*5+q(+pad)]            (51072 B)
    float  w1t[64][64];     // w1t[k][u] = W1[u][k]                 (16384 B)
    float2 zhalf[4][2][8];  // [q][warp-half][pair]                 (  512 B)
};

__device__ __forceinline__ float tanha(float x) {
    float r;
    asm("tanh.approx.f32 %0, %1;" : "=f"(r) : "f"(x));
    return r;
}
__device__ __forceinline__ float siga(float x) {
    return fmaf(0.5f, tanha(0.5f * x), 0.5f);
}

// 4 accumulators += pair-vector * scalar, via packed fma.rn.f32x2
__device__ __forceinline__ void gate4(float sw,
                                      float2 p0, float2 p1, float2 p2, float2 p3,
                                      float2& a0, float2& a1, float2& a2, float2& a3) {
    asm("{\n\t"
        ".reg .b64 rb, rx, ra;\n\t"
        "mov.b64 rb, {%8,%8};\n\t"
        "mov.b64 rx, {%9,%10};  mov.b64 ra, {%0,%1}; fma.rn.f32x2 ra, rx, rb, ra; mov.b64 {%0,%1}, ra;\n\t"
        "mov.b64 rx, {%11,%12}; mov.b64 ra, {%2,%3}; fma.rn.f32x2 ra, rx, rb, ra; mov.b64 {%2,%3}, ra;\n\t"
        "mov.b64 rx, {%13,%14}; mov.b64 ra, {%4,%5}; fma.rn.f32x2 ra, rx, rb, ra; mov.b64 {%4,%5}, ra;\n\t"
        "mov.b64 rx, {%15,%16}; mov.b64 ra, {%6,%7}; fma.rn.f32x2 ra, rx, rb, ra; mov.b64 {%6,%7}, ra;\n\t"
        "}"
        : "+f"(a0.x), "+f"(a0.y), "+f"(a1.x), "+f"(a1.y),
          "+f"(a2.x), "+f"(a2.y), "+f"(a3.x), "+f"(a3.y)
        : "f"(sw),
          "f"(p0.x), "f"(p0.y), "f"(p1.x), "f"(p1.y),
          "f"(p2.x), "f"(p2.y), "f"(p3.x), "f"(p3.y));
}

// LSTM cell, 8 pairs. XREG: k=2 (x2) / k=3 (x3) from registers (gen phase).
template<bool XREG>
__device__ __forceinline__ void lstm_step8(const SMem* s, int u, int q, int ph,
                                           const float2 x2[8], const float2 x3[8],
                                           float bi, float bf, float bg, float bo,
                                           float2 c8[8], float2 h8[8]) {
    float2 ai[8], af8[8], ag[8], ao[8];
#pragma unroll
    for (int p = 0; p < 8; ++p) {
        ai[p] = make_float2(bi, bi);
        af8[p] = make_float2(bf, bf);
        ag[p] = make_float2(bg, bg);
        ao[p] = make_float2(bo, bo);
    }
    const float4* wp = &s->wpack[0][u];       // stride 64 float4 per k
    const float4* xp = &s->xbuf[ph][q];       // +k*21, sets at +0,+5,+10,+15

    auto doK = [&](float4 w, float4 X0, float4 X1, float4 X2, float4 X3) {
        float2 p0 = make_float2(X0.x, X0.y), p1 = make_float2(X0.z, X0.w);
        float2 p2 = make_float2(X1.x, X1.y), p3 = make_float2(X1.z, X1.w);
        float2 p4 = make_float2(X2.x, X2.y), p5 = make_float2(X2.z, X2.w);
        float2 p6 = make_float2(X3.x, X3.y), p7 = make_float2(X3.z, X3.w);
        gate4(w.x, p0, p1, p2, p3, ai[0], ai[1], ai[2], ai[3]);
        gate4(w.x, p4, p5, p6, p7, ai[4], ai[5], ai[6], ai[7]);
        gate4(w.y, p0, p1, p2, p3, af8[0], af8[1], af8[2], af8[3]);
        gate4(w.y, p4, p5, p6, p7, af8[4], af8[5], af8[6], af8[7]);
        gate4(w.z, p0, p1, p2, p3, ag[0], ag[1], ag[2], ag[3]);
        gate4(w.z, p4, p5, p6, p7, ag[4], ag[5], ag[6], ag[7]);
        gate4(w.w, p0, p1, p2, p3, ao[0], ao[1], ao[2], ao[3]);
        gate4(w.w, p4, p5, p6, p7, ao[4], ao[5], ao[6], ao[7]);
    };
    auto doKreg = [&](float4 w, const float2 x[8]) {
        gate4(w.x, x[0], x[1], x[2], x[3], ai[0], ai[1], ai[2], ai[3]);
        gate4(w.x, x[4], x[5], x[6], x[7], ai[4], ai[5], ai[6], ai[7]);
        gate4(w.y, x[0], x[1], x[2], x[3], af8[0], af8[1], af8[2], af8[3]);
        gate4(w.y, x[4], x[5], x[6], x[7], af8[4], af8[5], af8[6], af8[7]);
        gate4(w.z, x[0], x[1], x[2], x[3], ag[0], ag[1], ag[2], ag[3]);
        gate4(w.z, x[4], x[5], x[6], x[7], ag[4], ag[5], ag[6], ag[7]);
        gate4(w.w, x[0], x[1], x[2], x[3], ao[0], ao[1], ao[2], ao[3]);
        gate4(w.w, x[4], x[5], x[6], x[7], ao[4], ao[5], ao[6], ao[7]);
    };

    doK(wp[0], xp[0], xp[5], xp[10], xp[15]);                       // k=0
    doK(wp[64], xp[21], xp[26], xp[31], xp[36]);                    // k=1
    if (XREG) {
        doKreg(wp[2 * 64], x2);                                     // k=2 (dp)
        doKreg(wp[3 * 64], x3);                                     // k=3 (dist)
    } else {
        doK(wp[2 * 64], xp[42], xp[47], xp[52], xp[57]);
        doK(wp[3 * 64], xp[63], xp[68], xp[73], xp[78]);
    }
    // pipelined k = 4..75
    float4 wc = wp[4 * 64];
    float4 a0 = xp[4 * 21], a1 = xp[4 * 21 + 5], a2 = xp[4 * 21 + 10], a3 = xp[4 * 21 + 15];
#pragma unroll 4
    for (int k = 4; k < 75; ++k) {
        float4 wn = wp[(k + 1) * 64];
        float4 n0 = xp[(k + 1) * 21],      n1 = xp[(k + 1) * 21 + 5];
        float4 n2 = xp[(k + 1) * 21 + 10], n3 = xp[(k + 1) * 21 + 15];
        doK(wc, a0, a1, a2, a3);
        wc = wn; a0 = n0; a1 = n1; a2 = n2; a3 = n3;
    }
    doK(wc, a0, a1, a2, a3);                                        // k=75

#pragma unroll
    for (int p = 0; p < 8; ++p) {
        float ix = siga(ai[p].x), fx = siga(af8[p].x), gx = tanha(ag[p].x), ox = siga(ao[p].x);
        c8[p].x = fmaf(fx, c8[p].x, ix * gx);
        h8[p].x = ox * tanha(c8[p].x);
        float iy = siga(ai[p].y), fy = siga(af8[p].y), gy = tanha(ag[p].y), oy = siga(ao[p].y);
        c8[p].y = fmaf(fy, c8[p].y, iy * gy);
        h8[p].y = oy * tanha(c8[p].y);
    }
}

__global__ void __launch_bounds__(NTHREADS, 1)
lstm_fused(const float* __restrict__ noise, const float* __restrict__ hist,
           const float* __restrict__ gap,   const float* __restrict__ W_ih,
           const float* __restrict__ W_hh,  const float* __restrict__ b_ih,
           const float* __restrict__ b_hh,  const float* __restrict__ W1,
           const float* __restrict__ b1,    const float* __restrict__ W2,
           const float* __restrict__ b2,    float* __restrict__ out) {
    extern __shared__ char smraw[];
    SMem* s = reinterpret_cast<SMem*>(smraw);

    const int tid = threadIdx.x;
    const int u   = tid & 63;          // hidden unit
    const int q   = tid >> 6;          // row group (0..3)
    const int lane = tid & 31;
    const int wh  = (tid >> 5) & 1;    // warp half (u<32 vs u>=32)
    const int blockRow = blockIdx.x * ROWS_PER_CTA;
    const int R = blockRow + 16 * q;   // rows R..R+15

    // ---- stage weights (transposed, gate-packed) ----
    for (int idx = tid; idx < 76 * 64; idx += NTHREADS) {
        int k = idx >> 6, uu = idx & 63;
        float4 w;
        if (k < 12) {
            w.x = W_ih[uu * 12 + k];
            w.y = W_ih[(64 + uu) * 12 + k];
            w.z = W_ih[(128 + uu) * 12 + k];
            w.w = W_ih[(192 + uu) * 12 + k];
        } else {
            int kk = k - 12;
            w.x = W_hh[uu * 64 + kk];
            w.y = W_hh[(64 + uu) * 64 + kk];
            w.z = W_hh[(128 + uu) * 64 + kk];
            w.w = W_hh[(192 + uu) * 64 + kk];
        }
        s->wpack[k][uu] = w;
    }
    for (int idx = tid; idx < 64 * 64; idx += NTHREADS) {
        int uu = idx >> 6, k = idx & 63;
        s->w1t[k][uu] = W1[idx];
    }
    // h0 = 0 in phase 0 (k = 12..75)
    for (int idx = tid; idx < 64 * 4; idx += NTHREADS) {
        int k = idx >> 2, st = idx & 3;
#pragma unroll
        for (int qq = 0; qq < 4; ++qq)
            s->xbuf[0][(12 + k) * 21 + st * 5 + qq] = make_float4(0.f, 0.f, 0.f, 0.f);
    }
    // ---- copy hist_x into out[:, :64, :] ----
    for (int idx = tid; idx < ROWS_PER_CTA * 192; idx += NTHREADS) {
        int rl = idx / 192, j = idx % 192;
        out[(size_t)(blockRow + rl) * OUTSTR + j] = hist[(size_t)(blockRow + rl) * 192 + j];
    }

    const float bi = b_ih[u] + b_hh[u];
    const float bf = b_ih[64 + u] + b_hh[64 + u];
    const float bg = b_ih[128 + u] + b_hh[128 + u];
    const float bo = b_ih[192 + u] + b_hh[192 + u];
    const float b1v = b1[u];
    const float w2v = W2[u];
    const float b2v = b2[0];

    float2 c8[8], h8[8], dist8[8], pfv[8];
#pragma unroll
    for (int p = 0; p < 8; ++p) {
        c8[p] = make_float2(0.f, 0.f);
        dist8[p] = make_float2(0.f, 0.f);
        pfv[p] = make_float2(0.f, 0.f);
    }

    // ---- prefetchers: only u<12 threads touch global memory ----
    auto pre_cond = [&](int j) {
        if (u < 4) {
            int ch = (u == 3) ? 2 : u;      // u==3 tracks ch2 for the dist cumsum
#pragma unroll
            for (int p = 0; p < 8; ++p) {
                const float* hp = hist + (size_t)(R + 2 * p) * 192 + j * 3 + ch;
                pfv[p].x = hp[0];
                pfv[p].y = hp[192];
            }
        } else if (u < 12) {
            int ch = u - 4;
#pragma unroll
            for (int p = 0; p < 8; ++p) {
                const float* np = noise + (size_t)(R + 2 * p) * 2048 + j * 8 + ch;
                pfv[p].x = np[0];
                pfv[p].y = np[2048];
            }
        }
    };
    auto pre_gen = [&](int t) {
        if (u < 2) {
#pragma unroll
            for (int p = 0; p < 8; ++p) {
                const float* gp = gap + (size_t)(R + 2 * p) * 386 + t * 2 + u;
                pfv[p].x = gp[0];
                pfv[p].y = gp[386];
            }
        } else if (u >= 4 && u < 12) {
            if (t < 192) {
                int ch = u - 4;
#pragma unroll
                for (int p = 0; p < 8; ++p) {
                    const float* np = noise + (size_t)(R + 2 * p) * 2048 + (64 + t) * 8 + ch;
                    pfv[p].x = np[0];
                    pfv[p].y = np[2048];
                }
            } else {
#pragma unroll
                for (int p = 0; p < 8; ++p) pfv[p] = make_float2(0.f, 0.f);
            }
        }
    };
    auto write_x4 = [&](int ph, int k, const float2 v[8]) {
        float4* dst = &s->xbuf[ph][k * 21 + q];
        dst[0]  = make_float4(v[0].x, v[0].y, v[1].x, v[1].y);
        dst[5]  = make_float4(v[2].x, v[2].y, v[3].x, v[3].y);
        dst[10] = make_float4(v[4].x, v[4].y, v[5].x, v[5].y);
        dst[15] = make_float4(v[6].x, v[6].y, v[7].x, v[7].y);
    };

    pre_cond(0);
    __syncthreads();   // staging + h0 visible

    // ================= conditioning (64 steps, 1 barrier each) =================
    for (int j = 0; j < 64; ++j) {
        int ph = j & 1;
        if (u == 3) {                     // dist = inclusive cumsum of hist ch2
#pragma unroll
            for (int p = 0; p < 8; ++p) {
                dist8[p].x += pfv[p].x;
                dist8[p].y += pfv[p].y;
            }
            write_x4(ph, 3, dist8);
        } else if (u < 12) {
            write_x4(ph, u, pfv);
        }
        __syncthreads();                  // inputs + previous h visible
        if (j < 63) pre_cond(j + 1); else pre_gen(0);
        lstm_step8<false>(s, u, q, ph, nullptr, nullptr, bi, bf, bg, bo, c8, h8);
        write_x4(ph ^ 1, 12 + u, h8);
    }
    __syncthreads();   // last h (phase 0) + last dist (phase 1) visible

    // all threads pick up final dist from phase 1, k=3
    {
        const float4* src = &s->xbuf[1][3 * 21 + q];
#pragma unroll
        for (int st = 0; st < 4; ++st) {
            float4 v = src[st * 5];
            dist8[2 * st]     = make_float2(v.x, v.y);
            dist8[2 * st + 1] = make_float2(v.z, v.w);
        }
    }

    // ================= generation (193 steps, 2 barriers each) =================
    for (int t = 0; t <= 192; ++t) {
        int ph = t & 1;
        // --- MLP head: a[u][row] = b1 + sum_k h[k][row]*W1[u][k] ---
        float2 az[8];
#pragma unroll
        for (int p = 0; p < 8; ++p) az[p] = make_float2(b1v, b1v);
        {
            const float*  w1p = &s->w1t[0][u];
            const float4* hp4 = &s->xbuf[ph][12 * 21 + q];
#pragma unroll 4
            for (int k = 0; k < 64; ++k) {
                float wv = w1p[k * 64];
                float4 X0 = hp4[k * 21],      X1 = hp4[k * 21 + 5];
                float4 X2 = hp4[k * 21 + 10], X3 = hp4[k * 21 + 15];
                gate4(wv, make_float2(X0.x, X0.y), make_float2(X0.z, X0.w),
                      make_float2(X1.x, X1.y), make_float2(X1.z, X1.w),
                      az[0], az[1], az[2], az[3]);
                gate4(wv, make_float2(X2.x, X2.y), make_float2(X2.z, X2.w),
                      make_float2(X3.x, X3.y), make_float2(X3.z, X3.w),
                      az[4], az[5], az[6], az[7]);
            }
        }
        float2 part[8];
#pragma unroll
        for (int p = 0; p < 8; ++p)
            part[p] = make_float2(tanha(az[p].x) * w2v, tanha(az[p].y) * w2v);
        // reduce over this warp's 32 u's (all lanes share q)
#pragma unroll
        for (int p = 0; p < 8; ++p) {
#pragma unroll
            for (int m = 16; m >= 1; m >>= 1) {
                part[p].x += __shfl_xor_sync(0xffffffffu, part[p].x, m);
                part[p].y += __shfl_xor_sync(0xffffffffu, part[p].y, m);
            }
        }
        if (lane == 0) {
#pragma unroll
            for (int p = 0; p < 8; ++p) s->zhalf[q][wh][p] = part[p];
        }
        // write gap/noise inputs for this step before the same barrier
        if (u < 2 || (u >= 4 && u < 12)) write_x4(ph, u, pfv);
        __syncthreads();                  // zhalf + x inputs visible
        // every thread computes dp for its rows (redundant but cheap)
        float2 dp[8];
#pragma unroll
        for (int p = 0; p < 8; ++p) {
            float2 za = s->zhalf[q][0][p];
            float2 zb = s->zhalf[q][1][p];
            dp[p].x = 24.f * tanha(za.x + zb.x + b2v);
            dp[p].y = 24.f * tanha(za.y + zb.y + b2v);
            dist8[p].x += dp[p].x;
            dist8[p].y += dp[p].y;
        }
        int trow = (64 + t) * 3;
        if (u < 2) {
#pragma unroll
            for (int p = 0; p < 8; ++p) {
                out[(size_t)(R + 2 * p) * OUTSTR + trow + u] = pfv[p].x;
                out[(size_t)(R + 2 * p + 1) * OUTSTR + trow + u] = pfv[p].y;
            }
        } else if (u == 2) {
#pragma unroll
            for (int p = 0; p < 8; ++p) {
                out[(size_t)(R + 2 * p) * OUTSTR + trow + 2] = dp[p].x;
                out[(size_t)(R + 2 * p + 1) * OUTSTR + trow + 2] = dp[p].y;
            }
        }
        if (t == 192) break;              // last LSTM update is dead in the reference
        pre_gen(t + 1);
        lstm_step8<true>(s, u, q, ph, dp, dist8, bi, bf, bg, bo, c8, h8);
        write_x4(ph ^ 1, 12 + u, h8);
        __syncthreads();                  // h visible for next MLP
    }
}

extern "C" void kernel_launch(void* const* d_in, const int* in_sizes, int n_in,
                              void* d_out, int out_size) {
    const float* noise = (const float*)d_in[0];
    const float* hist  = (const float*)d_in[1];
    const float* gap   = (const float*)d_in[2];
    const float* W_ih  = (const float*)d_in[3];
    const float* W_hh  = (const float*)d_in[4];
    const float* b_ih  = (const float*)d_in[5];
    const float* b_hh  = (const float*)d_in[6];
    const float* W1    = (const float*)d_in[7];
    const float* b1    = (const float*)d_in[8];
    const float* W2    = (const float*)d_in[9];
    const float* b2    = (const float*)d_in[10];
    float* out = (float*)d_out;

    size_t smem = sizeof(SMem);
    cudaFuncSetAttribute(lstm_fused, cudaFuncAttributeMaxDynamicSharedMemorySize, (int)smem);
    lstm_fused<<<NCTA, NTHREADS, smem>>>(noise, hist, gap, W_ih, W_hh, b_ih, b_hh,
                                         W1, b1, W2, b2, out);
}

// round 12
// speedup vs baseline: 1.2620x; 1.1677x over previous
#include <cuda_runtime.h>

#define NTHREADS 256
#define ROWS_PER_CTA 64
#define NCTA 128          // 8192 / 64
#define OUTSTR 771        // 257*3

// CTA split into two independent halves of 128 threads (rows 0-31 / 32-63).
// Within a half: u = htid & 63 (hidden unit), q = 2*half + (htid>>6) (row group).
// Thread owns 16 rows (8 float2 pairs). Warp = 32 consecutive u, same q.
// Halves sync only via named barriers -> they drift and overlap pipes.
struct SMem {
    float4 wpack[76][64];   // {Wi,Wf,Wg,Wo}[.,k] for unit u        (77824 B)
    float4 xbuf[2][76*21];  // [phase][k*21 + set*5 + q]            (51072 B)
    float  w1t[64][64];     // w1t[k][u] = W1[u][k]                 (16384 B)
    float2 zhalf[4][2][8];  // [q][warp-half][pair]                 (  512 B)
};

__device__ __forceinline__ void bar_half(int half) {
    asm volatile("bar.sync %0, 128;" :: "r"(half + 1) : "memory");
}

__device__ __forceinline__ float tanha(float x) {
    float r;
    asm("tanh.approx.f32 %0, %1;" : "=f"(r) : "f"(x));
    return r;
}
__device__ __forceinline__ float siga(float x) {
    return fmaf(0.5f, tanha(0.5f * x), 0.5f);
}

// 4 accumulators += pair-vector * scalar, via packed fma.rn.f32x2
__device__ __forceinline__ void gate4(float sw,
                                      float2 p0, float2 p1, float2 p2, float2 p3,
                                      float2& a0, float2& a1, float2& a2, float2& a3) {
    asm("{\n\t"
        ".reg .b64 rb, rx, ra;\n\t"
        "mov.b64 rb, {%8,%8};\n\t"
        "mov.b64 rx, {%9,%10};  mov.b64 ra, {%0,%1}; fma.rn.f32x2 ra, rx, rb, ra; mov.b64 {%0,%1}, ra;\n\t"
        "mov.b64 rx, {%11,%12}; mov.b64 ra, {%2,%3}; fma.rn.f32x2 ra, rx, rb, ra; mov.b64 {%2,%3}, ra;\n\t"
        "mov.b64 rx, {%13,%14}; mov.b64 ra, {%4,%5}; fma.rn.f32x2 ra, rx, rb, ra; mov.b64 {%4,%5}, ra;\n\t"
        "mov.b64 rx, {%15,%16}; mov.b64 ra, {%6,%7}; fma.rn.f32x2 ra, rx, rb, ra; mov.b64 {%6,%7}, ra;\n\t"
        "}"
        : "+f"(a0.x), "+f"(a0.y), "+f"(a1.x), "+f"(a1.y),
          "+f"(a2.x), "+f"(a2.y), "+f"(a3.x), "+f"(a3.y)
        : "f"(sw),
          "f"(p0.x), "f"(p0.y), "f"(p1.x), "f"(p1.y),
          "f"(p2.x), "f"(p2.y), "f"(p3.x), "f"(p3.y));
}

// LSTM cell, 8 pairs. XREG: k=2 (x2) / k=3 (x3) from registers (gen phase).
template<bool XREG>
__device__ __forceinline__ void lstm_step8(const SMem* s, int u, int q, int ph,
                                           const float2 x2[8], const float2 x3[8],
                                           float bi, float bf, float bg, float bo,
                                           float2 c8[8], float2 h8[8]) {
    float2 ai[8], af8[8], ag[8], ao[8];
#pragma unroll
    for (int p = 0; p < 8; ++p) {
        ai[p] = make_float2(bi, bi);
        af8[p] = make_float2(bf, bf);
        ag[p] = make_float2(bg, bg);
        ao[p] = make_float2(bo, bo);
    }
    const float4* wp = &s->wpack[0][u];       // stride 64 float4 per k
    const float4* xp = &s->xbuf[ph][q];       // +k*21, sets at +0,+5,+10,+15

    auto doK = [&](float4 w, float4 X0, float4 X1, float4 X2, float4 X3) {
        float2 p0 = make_float2(X0.x, X0.y), p1 = make_float2(X0.z, X0.w);
        float2 p2 = make_float2(X1.x, X1.y), p3 = make_float2(X1.z, X1.w);
        float2 p4 = make_float2(X2.x, X2.y), p5 = make_float2(X2.z, X2.w);
        float2 p6 = make_float2(X3.x, X3.y), p7 = make_float2(X3.z, X3.w);
        gate4(w.x, p0, p1, p2, p3, ai[0], ai[1], ai[2], ai[3]);
        gate4(w.x, p4, p5, p6, p7, ai[4], ai[5], ai[6], ai[7]);
        gate4(w.y, p0, p1, p2, p3, af8[0], af8[1], af8[2], af8[3]);
        gate4(w.y, p4, p5, p6, p7, af8[4], af8[5], af8[6], af8[7]);
        gate4(w.z, p0, p1, p2, p3, ag[0], ag[1], ag[2], ag[3]);
        gate4(w.z, p4, p5, p6, p7, ag[4], ag[5], ag[6], ag[7]);
        gate4(w.w, p0, p1, p2, p3, ao[0], ao[1], ao[2], ao[3]);
        gate4(w.w, p4, p5, p6, p7, ao[4], ao[5], ao[6], ao[7]);
    };
    auto doKreg = [&](float4 w, const float2 x[8]) {
        gate4(w.x, x[0], x[1], x[2], x[3], ai[0], ai[1], ai[2], ai[3]);
        gate4(w.x, x[4], x[5], x[6], x[7], ai[4], ai[5], ai[6], ai[7]);
        gate4(w.y, x[0], x[1], x[2], x[3], af8[0], af8[1], af8[2], af8[3]);
        gate4(w.y, x[4], x[5], x[6], x[7], af8[4], af8[5], af8[6], af8[7]);
        gate4(w.z, x[0], x[1], x[2], x[3], ag[0], ag[1], ag[2], ag[3]);
        gate4(w.z, x[4], x[5], x[6], x[7], ag[4], ag[5], ag[6], ag[7]);
        gate4(w.w, x[0], x[1], x[2], x[3], ao[0], ao[1], ao[2], ao[3]);
        gate4(w.w, x[4], x[5], x[6], x[7], ao[4], ao[5], ao[6], ao[7]);
    };

    doK(wp[0], xp[0], xp[5], xp[10], xp[15]);                       // k=0
    doK(wp[64], xp[21], xp[26], xp[31], xp[36]);                    // k=1
    if (XREG) {
        doKreg(wp[2 * 64], x2);                                     // k=2 (dp)
        doKreg(wp[3 * 64], x3);                                     // k=3 (dist)
    } else {
        doK(wp[2 * 64], xp[42], xp[47], xp[52], xp[57]);
        doK(wp[3 * 64], xp[63], xp[68], xp[73], xp[78]);
    }
    // pipelined k = 4..75
    float4 wc = wp[4 * 64];
    float4 a0 = xp[4 * 21], a1 = xp[4 * 21 + 5], a2 = xp[4 * 21 + 10], a3 = xp[4 * 21 + 15];
#pragma unroll 4
    for (int k = 4; k < 75; ++k) {
        float4 wn = wp[(k + 1) * 64];
        float4 n0 = xp[(k + 1) * 21],      n1 = xp[(k + 1) * 21 + 5];
        float4 n2 = xp[(k + 1) * 21 + 10], n3 = xp[(k + 1) * 21 + 15];
        doK(wc, a0, a1, a2, a3);
        wc = wn; a0 = n0; a1 = n1; a2 = n2; a3 = n3;
    }
    doK(wc, a0, a1, a2, a3);                                        // k=75

#pragma unroll
    for (int p = 0; p < 8; ++p) {
        float ix = siga(ai[p].x), fx = siga(af8[p].x), gx = tanha(ag[p].x), ox = siga(ao[p].x);
        c8[p].x = fmaf(fx, c8[p].x, ix * gx);
        h8[p].x = ox * tanha(c8[p].x);
        float iy = siga(ai[p].y), fy = siga(af8[p].y), gy = tanha(ag[p].y), oy = siga(ao[p].y);
        c8[p].y = fmaf(fy, c8[p].y, iy * gy);
        h8[p].y = oy * tanha(c8[p].y);
    }
}

__global__ void __launch_bounds__(NTHREADS, 1)
lstm_fused(const float* __restrict__ noise, const float* __restrict__ hist,
           const float* __restrict__ gap,   const float* __restrict__ W_ih,
           const float* __restrict__ W_hh,  const float* __restrict__ b_ih,
           const float* __restrict__ b_hh,  const float* __restrict__ W1,
           const float* __restrict__ b1,    const float* __restrict__ W2,
           const float* __restrict__ b2,    float* __restrict__ out) {
    extern __shared__ char smraw[];
    SMem* s = reinterpret_cast<SMem*>(smraw);

    const int tid  = threadIdx.x;
    const int half = tid >> 7;             // 0: rows 0-31, 1: rows 32-63
    const int htid = tid & 127;
    const int u    = htid & 63;            // hidden unit
    const int q    = 2 * half + (htid >> 6); // row group (0..3)
    const int lane = tid & 31;
    const int wh   = (htid >> 5) & 1;      // warp half within q (u<32 vs u>=32)
    const int blockRow = blockIdx.x * ROWS_PER_CTA;
    const int R = blockRow + 16 * q;       // rows R..R+15

    // ---- stage weights (transposed, gate-packed) ----
    for (int idx = tid; idx < 76 * 64; idx += NTHREADS) {
        int k = idx >> 6, uu = idx & 63;
        float4 w;
        if (k < 12) {
            w.x = W_ih[uu * 12 + k];
            w.y = W_ih[(64 + uu) * 12 + k];
            w.z = W_ih[(128 + uu) * 12 + k];
            w.w = W_ih[(192 + uu) * 12 + k];
        } else {
            int kk = k - 12;
            w.x = W_hh[uu * 64 + kk];
            w.y = W_hh[(64 + uu) * 64 + kk];
            w.z = W_hh[(128 + uu) * 64 + kk];
            w.w = W_hh[(192 + uu) * 64 + kk];
        }
        s->wpack[k][uu] = w;
    }
    for (int idx = tid; idx < 64 * 64; idx += NTHREADS) {
        int uu = idx >> 6, k = idx & 63;
        s->w1t[k][uu] = W1[idx];
    }
    // h0 = 0 in phase 0 (k = 12..75)
    for (int idx = tid; idx < 64 * 4; idx += NTHREADS) {
        int k = idx >> 2, st = idx & 3;
#pragma unroll
        for (int qq = 0; qq < 4; ++qq)
            s->xbuf[0][(12 + k) * 21 + st * 5 + qq] = make_float4(0.f, 0.f, 0.f, 0.f);
    }
    // ---- copy hist_x into out[:, :64, :] ----
    for (int idx = tid; idx < ROWS_PER_CTA * 192; idx += NTHREADS) {
        int rl = idx / 192, j = idx % 192;
        out[(size_t)(blockRow + rl) * OUTSTR + j] = hist[(size_t)(blockRow + rl) * 192 + j];
    }

    const float bi = b_ih[u] + b_hh[u];
    const float bf = b_ih[64 + u] + b_hh[64 + u];
    const float bg = b_ih[128 + u] + b_hh[128 + u];
    const float bo = b_ih[192 + u] + b_hh[192 + u];
    const float b1v = b1[u];
    const float w2v = W2[u];
    const float b2v = b2[0];

    float2 c8[8], h8[8], dist8[8], pfv[8];
#pragma unroll
    for (int p = 0; p < 8; ++p) {
        c8[p] = make_float2(0.f, 0.f);
        dist8[p] = make_float2(0.f, 0.f);
        pfv[p] = make_float2(0.f, 0.f);
    }

    // ---- prefetchers: only u<12 threads touch global memory ----
    auto pre_cond = [&](int j) {
        if (u < 4) {
            int ch = (u == 3) ? 2 : u;      // u==3 tracks ch2 for the dist cumsum
#pragma unroll
            for (int p = 0; p < 8; ++p) {
                const float* hp = hist + (size_t)(R + 2 * p) * 192 + j * 3 + ch;
                pfv[p].x = hp[0];
                pfv[p].y = hp[192];
            }
        } else if (u < 12) {
            int ch = u - 4;
#pragma unroll
            for (int p = 0; p < 8; ++p) {
                const float* np = noise + (size_t)(R + 2 * p) * 2048 + j * 8 + ch;
                pfv[p].x = np[0];
                pfv[p].y = np[2048];
            }
        }
    };
    auto pre_gen = [&](int t) {
        if (u < 2) {
#pragma unroll
            for (int p = 0; p < 8; ++p) {
                const float* gp = gap + (size_t)(R + 2 * p) * 386 + t * 2 + u;
                pfv[p].x = gp[0];
                pfv[p].y = gp[386];
            }
        } else if (u >= 4 && u < 12) {
            if (t < 192) {
                int ch = u - 4;
#pragma unroll
                for (int p = 0; p < 8; ++p) {
                    const float* np = noise + (size_t)(R + 2 * p) * 2048 + (64 + t) * 8 + ch;
                    pfv[p].x = np[0];
                    pfv[p].y = np[2048];
                }
            } else {
#pragma unroll
                for (int p = 0; p < 8; ++p) pfv[p] = make_float2(0.f, 0.f);
            }
        }
    };
    auto write_x4 = [&](int ph, int k, const float2 v[8]) {
        float4* dst = &s->xbuf[ph][k * 21 + q];
        dst[0]  = make_float4(v[0].x, v[0].y, v[1].x, v[1].y);
        dst[5]  = make_float4(v[2].x, v[2].y, v[3].x, v[3].y);
        dst[10] = make_float4(v[4].x, v[4].y, v[5].x, v[5].y);
        dst[15] = make_float4(v[6].x, v[6].y, v[7].x, v[7].y);
    };

    pre_cond(0);
    __syncthreads();   // staging + h0 visible to both halves (last full-CTA barrier)

    // ================= conditioning (64 steps, 1 half-barrier each) =================
    for (int j = 0; j < 64; ++j) {
        int ph = j & 1;
        if (u == 3) {                     // dist = inclusive cumsum of hist ch2
#pragma unroll
            for (int p = 0; p < 8; ++p) {
                dist8[p].x += pfv[p].x;
                dist8[p].y += pfv[p].y;
            }
            write_x4(ph, 3, dist8);
        } else if (u < 12) {
            write_x4(ph, u, pfv);
        }
        bar_half(half);                   // inputs + previous h visible (own half)
        if (j < 63) pre_cond(j + 1); else pre_gen(0);
        lstm_step8<false>(s, u, q, ph, nullptr, nullptr, bi, bf, bg, bo, c8, h8);
        write_x4(ph ^ 1, 12 + u, h8);
    }
    bar_half(half);   // last h (phase 0) + last dist (phase 1) visible

    // all threads pick up final dist from phase 1, k=3 (own q)
    {
        const float4* src = &s->xbuf[1][3 * 21 + q];
#pragma unroll
        for (int st = 0; st < 4; ++st) {
            float4 v = src[st * 5];
            dist8[2 * st]     = make_float2(v.x, v.y);
            dist8[2 * st + 1] = make_float2(v.z, v.w);
        }
    }

    // ================= generation (193 steps, 2 half-barriers each) =================
    for (int t = 0; t <= 192; ++t) {
        int ph = t & 1;
        // --- MLP head: a[u][row] = b1 + sum_k h[k][row]*W1[u][k] ---
        float2 az[8];
#pragma unroll
        for (int p = 0; p < 8; ++p) az[p] = make_float2(b1v, b1v);
        {
            const float*  w1p = &s->w1t[0][u];
            const float4* hp4 = &s->xbuf[ph][12 * 21 + q];
#pragma unroll 4
            for (int k = 0; k < 64; ++k) {
                float wv = w1p[k * 64];
                float4 X0 = hp4[k * 21],      X1 = hp4[k * 21 + 5];
                float4 X2 = hp4[k * 21 + 10], X3 = hp4[k * 21 + 15];
                gate4(wv, make_float2(X0.x, X0.y), make_float2(X0.z, X0.w),
                      make_float2(X1.x, X1.y), make_float2(X1.z, X1.w),
                      az[0], az[1], az[2], az[3]);
                gate4(wv, make_float2(X2.x, X2.y), make_float2(X2.z, X2.w),
                      make_float2(X3.x, X3.y), make_float2(X3.z, X3.w),
                      az[4], az[5], az[6], az[7]);
            }
        }
        float2 part[8];
#pragma unroll
        for (int p = 0; p < 8; ++p)
            part[p] = make_float2(tanha(az[p].x) * w2v, tanha(az[p].y) * w2v);
        // reduce over this warp's 32 u's (all lanes share q)
#pragma unroll
        for (int p = 0; p < 8; ++p) {
#pragma unroll
            for (int m = 16; m >= 1; m >>= 1) {
                part[p].x += __shfl_xor_sync(0xffffffffu, part[p].x, m);
                part[p].y += __shfl_xor_sync(0xffffffffu, part[p].y, m);
            }
        }
        if (lane == 0) {
#pragma unroll
            for (int p = 0; p < 8; ++p) s->zhalf[q][wh][p] = part[p];
        }
        // write gap/noise inputs for this step before the same barrier
        if (u < 2 || (u >= 4 && u < 12)) write_x4(ph, u, pfv);
        bar_half(half);                   // zhalf + x inputs visible (own half)
        // every thread computes dp for its rows (redundant but cheap)
        float2 dp[8];
#pragma unroll
        for (int p = 0; p < 8; ++p) {
            float2 za = s->zhalf[q][0][p];
            float2 zb = s->zhalf[q][1][p];
            dp[p].x = 24.f * tanha(za.x + zb.x + b2v);
            dp[p].y = 24.f * tanha(za.y + zb.y + b2v);
            dist8[p].x += dp[p].x;
            dist8[p].y += dp[p].y;
        }
        int trow = (64 + t) * 3;
        if (u < 2) {
#pragma unroll
            for (int p = 0; p < 8; ++p) {
                out[(size_t)(R + 2 * p) * OUTSTR + trow + u] = pfv[p].x;
                out[(size_t)(R + 2 * p + 1) * OUTSTR + trow + u] = pfv[p].y;
            }
        } else if (u == 2) {
#pragma unroll
            for (int p = 0; p < 8; ++p) {
                out[(size_t)(R + 2 * p) * OUTSTR + trow + 2] = dp[p].x;
                out[(size_t)(R + 2 * p + 1) * OUTSTR + trow + 2] = dp[p].y;
            }
        }
        if (t == 192) break;              // last LSTM update is dead in the reference
        pre_gen(t + 1);
        lstm_step8<true>(s, u, q, ph, dp, dist8, bi, bf, bg, bo, c8, h8);
        write_x4(ph ^ 1, 12 + u, h8);
        bar_half(half);                   // h visible for next MLP (own half)
    }
}

extern "C" void kernel_launch(void* const* d_in, const int* in_sizes, int n_in,
                              void* d_out, int out_size) {
    const float* noise = (const float*)d_in[0];
    const float* hist  = (const float*)d_in[1];
    const float* gap   = (const float*)d_in[2];
    const float* W_ih  = (const float*)d_in[3];
    const float* W_hh  = (const float*)d_in[4];
    const float* b_ih  = (const float*)d_in[5];
    const float* b_hh  = (const float*)d_in[6];
    const float* W1    = (const float*)d_in[7];
    const float* b1    = (const float*)d_in[8];
    const float* W2    = (const float*)d_in[9];
    const float* b2    = (const float*)d_in[10];
    float* out = (float*)d_out;

    size_t smem = sizeof(SMem);
    cudaFuncSetAttribute(lstm_fused, cudaFuncAttributeMaxDynamicSharedMemorySize, (int)smem);
    lstm_fused<<<NCTA, NTHREADS, smem>>>(noise, hist, gap, W_ih, W_hh, b_ih, b_hh,
                                         W1, b1, W2, b2, out);
}